// round 14
// baseline (speedup 1.0000x reference)
#include <cuda_runtime.h>
#include <cuda_bf16.h>
#include <cstdint>

#define NN 50000
#define EE 800000
#define GG 512
#define CC 128
#define NBLK 196          // ceil(NN/256) node tiles
#define CSRB 148          // CSR builder blocks (1/SM, co-resident)
#define SPB  592          // SpMV blocks (4/SM, co-resident)
#define TLB  148          // tail blocks (1/SM)
#define NTILE 391         // ceil(NN/128) stat tiles

// ---------------- scratch (static device arrays; no allocation) ----------------
__device__ float g_h0[NN*CC];
__device__ float g_h1[NN*CC];
__device__ float g_t1[NN*CC];
__device__ float g_t2[NN*CC];
__device__ float g_dis[NN];
__device__ int   g_hist[NN];
__device__ int   g_ptr[NN+1];
__device__ int   g_fill[NN];
__device__ int   g_bsum[NBLK];
__device__ int   g_syncC[8];         // csr barrier counters (self-reset)
__device__ int   g_syncS[4];         // spmv2 barrier counters (self-reset)
__device__ int   g_syncT[8];         // tail barrier counters (self-reset)
__device__ int2  g_epk[EE];          // packed CSR: (col, bits(norm))
__device__ float g_pool[GG*CC];
__device__ float g_cnt[GG];
__device__ float g_chsum[CC];
__device__ float g_chsq[CC];
__device__ float g_bna[CC];
__device__ float g_bnb[CC];
// split-bf16 weights for BOTH convs: [conv][n*384+k] (transposed, folded)
__device__ __align__(16) __nv_bfloat16 g_Bh[2][CC*384];
__device__ __align__(16) __nv_bfloat16 g_Bl[2][CC*384];

// ---------------- mma.sync helpers (baseline PTX, works at compute_103) --------
__device__ __forceinline__ void ldsm4(uint32_t* r, uint32_t addr) {
    asm volatile("ldmatrix.sync.aligned.m8n8.x4.shared.b16 {%0,%1,%2,%3}, [%4];"
                 : "=r"(r[0]), "=r"(r[1]), "=r"(r[2]), "=r"(r[3]) : "r"(addr));
}
__device__ __forceinline__ void mma16816(float* c, const uint32_t* a, const uint32_t* b) {
    asm volatile("mma.sync.aligned.m16n8k16.row.col.f32.bf16.bf16.f32 "
                 "{%0,%1,%2,%3}, {%4,%5,%6,%7}, {%8,%9}, {%0,%1,%2,%3};"
                 : "+f"(c[0]), "+f"(c[1]), "+f"(c[2]), "+f"(c[3])
                 : "r"(a[0]), "r"(a[1]), "r"(a[2]), "r"(a[3]), "r"(b[0]), "r"(b[1]));
}
__device__ __forceinline__ uint32_t smem_u32(const void* p) {
    uint32_t a;
    asm("{ .reg .u64 t; cvta.to.shared.u64 t, %1; cvt.u32.u64 %0, t; }" : "=r"(a) : "l"(p));
    return a;
}
#define CP_ASYNC16(dst, src) \
    asm volatile("cp.async.cg.shared.global [%0], [%1], 16;" \
                 :: "r"(dst), "l"(src) : "memory")
#define CP_COMMIT() asm volatile("cp.async.commit_group;" ::: "memory")
#define CP_WAIT0()  asm volatile("cp.async.wait_group 0;" ::: "memory")

// device-scope grid barrier for co-resident grids (all threads fence first)
__device__ __forceinline__ void gridbar(int* ctr, int nblk) {
    __threadfence();
    __syncthreads();
    if (threadIdx.x == 0) {
        atomicAdd(ctr, 1);
        while (atomicAdd(ctr, 0) < nblk) { }
    }
    __syncthreads();
}
// exit protocol: block 0 resets counters for graph replay
__device__ __forceinline__ void gridexit(int* ctr, int* arr, int na, int nblk, int b) {
    __threadfence();
    __syncthreads();
    if (threadIdx.x == 0) {
        atomicAdd(ctr, 1);
        if (b == 0) {
            while (atomicAdd(ctr, 0) < nblk) { }
            for (int i = 0; i < na; i++) arr[i] = 0;
            __threadfence();
        }
    }
}

// ---------------- fused CSR build + atom embedding + weight folds ----------------
__global__ void __launch_bounds__(256)
k_csr(const int* __restrict__ row, const int* __restrict__ col,
      const float* __restrict__ emb, const int* __restrict__ x,
      const float* __restrict__ WA, const float* __restrict__ WB) {
    __shared__ int sh[256];
    __shared__ int sb[256];
    int tid = threadIdx.x, b = blockIdx.x;
    int gt = b * 256 + tid;
    const int GT = CSRB * 256;
    int lane = tid & 31;
    int gw = gt >> 5;
    const int GW = GT >> 5;

    // E0: atom embedding (warp per node): h0[n,:] = sum_f emb[f, x[n,f], :]
    for (int n = gw; n < NN; n += GW) {
        int xf = (lane < 9) ? x[n * 9 + lane] : 0;
        float4 s = make_float4(0.f, 0.f, 0.f, 0.f);
#pragma unroll
        for (int f = 0; f < 9; f++) {
            int xv = __shfl_sync(0xffffffffu, xf, f);
            float4 e = ((const float4*)(emb + (size_t)((f * 119) + xv) * CC))[lane];
            s.x += e.x; s.y += e.y; s.z += e.z; s.w += e.w;
        }
        ((float4*)(g_h0 + (size_t)n * CC))[lane] = s;
    }
    // E1: fold both convs' weights -> split-bf16, transposed
    for (int i = gt; i < 2 * CC * 384; i += GT) {
        int which = i / (CC * 384);
        int rem = i - which * (CC * 384);
        int n = rem / 384, k = rem - n * 384;
        const float* W = which ? WB : WA;
        int blk = k >> 7, ci = k & 127;
        float w;
        if (blk == 0)      w = W[ci * 128 + n] - W[2 * 16384 + ci * 128 + n];
        else if (blk == 1) w = W[16384 + ci * 128 + n];
        else               w = 2.f * W[2 * 16384 + ci * 128 + n];
        __nv_bfloat16 hi = __float2bfloat16(w);
        g_Bh[which][n * 384 + k] = hi;
        g_Bl[which][n * 384 + k] = __float2bfloat16(w - __bfloat162float(hi));
    }
    // P0: zero histogram
    for (int n = gt; n < NN; n += GT) g_hist[n] = 0;
    gridbar(&g_syncC[0], CSRB);

    // P1: degree histogram
    for (int e = gt; e < EE; e += GT) atomicAdd(&g_hist[row[e]], 1);
    gridbar(&g_syncC[1], CSRB);

    // P2: per-node dis + per-tile sums
    for (int t = b; t < NBLK; t += CSRB) {
        int n = t * 256 + tid;
        int h = (n < NN) ? g_hist[n] : 0;
        if (n < NN) g_dis[n] = (h > 0) ? rsqrtf((float)h) : 0.f;
        sh[tid] = h;
        __syncthreads();
        for (int s = 128; s > 0; s >>= 1) {
            if (tid < s) sh[tid] += sh[tid + s];
            __syncthreads();
        }
        if (tid == 0) g_bsum[t] = sh[0];
        __syncthreads();
    }
    gridbar(&g_syncC[2], CSRB);

    // P3: offsets — every block redundantly scans tile sums, then local scans
    int bv = (tid < NBLK) ? g_bsum[tid] : 0;
    sb[tid] = bv;
    __syncthreads();
    for (int o = 1; o < 256; o <<= 1) {
        int xx = (tid >= o) ? sb[tid - o] : 0;
        __syncthreads();
        sb[tid] += xx;
        __syncthreads();
    }
    for (int t = b; t < NBLK; t += CSRB) {
        int base = (t == 0) ? 0 : sb[t - 1];
        int n = t * 256 + tid;
        int v = (n < NN) ? g_hist[n] : 0;
        sh[tid] = v;
        __syncthreads();
        for (int o = 1; o < 256; o <<= 1) {
            int xx = (tid >= o) ? sh[tid - o] : 0;
            __syncthreads();
            sh[tid] += xx;
            __syncthreads();
        }
        int off = base + sh[tid] - v;
        if (n < NN) { g_ptr[n] = off; g_fill[n] = off; }
        if (n == NN - 1) g_ptr[NN] = off + v;
        __syncthreads();
    }
    gridbar(&g_syncC[3], CSRB);

    // P4: scatter packed (col, norm)
    for (int e = gt; e < EE; e += GT) {
        int r = row[e], c = col[e];
        int pos = atomicAdd(&g_fill[r], 1);
        float w = -(g_dis[r] * g_dis[c]);
        g_epk[pos] = make_int2(c, __float_as_int(w));
    }
    gridexit(&g_syncC[4], g_syncC, 8, CSRB, b);
}

// SpMV row body (proven R7/R12 form; at LTS cap — do not touch)
__device__ __forceinline__ void spmv_row(const float* __restrict__ src,
                                         float* __restrict__ dst, int w, int lane) {
    int s = g_ptr[w], e = g_ptr[w + 1];
    float4 acc = make_float4(0.f, 0.f, 0.f, 0.f);
    for (int j = s; j < e; j += 32) {
        int idx = j + lane;
        int2 pk = (idx < e) ? g_epk[idx] : make_int2(0, 0);
        int cnt = min(32, e - j);
        for (int k = 0; k < cnt; k++) {
            int ck = __shfl_sync(0xffffffffu, pk.x, k);
            float wk = __uint_as_float(__shfl_sync(0xffffffffu, (unsigned)pk.y, k));
            float4 v = ((const float4*)(src + (size_t)ck * CC))[lane];
            acc.x = fmaf(wk, v.x, acc.x);
            acc.y = fmaf(wk, v.y, acc.y);
            acc.z = fmaf(wk, v.z, acc.z);
            acc.w = fmaf(wk, v.w, acc.w);
        }
    }
    ((float4*)(dst + (size_t)w * CC))[lane] = acc;
}

// fused double SpMV: t1 = L src; grid barrier; t2 = L t1  (persistent, 4 CTAs/SM)
__global__ void __launch_bounds__(256, 4)
k_spmv2(const float* __restrict__ src, float* __restrict__ t1, float* __restrict__ t2) {
    int tid = threadIdx.x, b = blockIdx.x;
    int gw = (b * 256 + tid) >> 5;
    int lane = tid & 31;
    const int NW = SPB * 8;

    for (int w = gw; w < NN; w += NW) spmv_row(src, t1, w, lane);
    gridbar(&g_syncS[0], SPB);
    for (int w = gw; w < NN; w += NW) spmv_row(t1, t2, w, lane);
    gridexit(&g_syncS[1], g_syncS, 4, SPB, b);
}

// double-buffered mma.sync split-bf16 GEMM: out = relu([A0|A1|A2] @ Bmod^T + bias)
// (byte-identical mainloop to R13's proven kernel)
#define BSTR 80
#define PLANE (128 * BSTR)
#define STAGE (4 * PLANE)
__global__ void __launch_bounds__(256, 2)
k_gemm(const float* __restrict__ A0, const float* __restrict__ A1,
       const float* __restrict__ A2, const __nv_bfloat16* __restrict__ Bh_,
       const __nv_bfloat16* __restrict__ Bl_, const float* __restrict__ bias,
       float* __restrict__ out)
{
    extern __shared__ char sm[];
    uint32_t sb = smem_u32(sm);
    char* smc = sm;

    int tid = threadIdx.x;
    int lane = tid & 31, wid = tid >> 5;
    int wm = (wid & 3) * 32;
    int wn = (wid >> 2) * 64;
    int m0 = blockIdx.x * 128;

    float acc[2][8][4];
#pragma unroll
    for (int mi = 0; mi < 2; mi++)
#pragma unroll
        for (int nj = 0; nj < 8; nj++)
#pragma unroll
            for (int q = 0; q < 4; q++) acc[mi][nj][q] = 0.f;

    const float* srcs[3] = {A0, A1, A2};
    const char* BhC = (const char*)Bh_;
    const char* BlC = (const char*)Bl_;

    int rb = tid >> 3;
    int q  = tid & 7;
    int n0 = tid >> 2,  p0 = tid & 3;
    int n1 = (tid + 256) >> 2, p1 = (tid + 256) & 3;

    float4 pa[4];

    {
        const float4* S4 = (const float4*)srcs[0];
#pragma unroll
        for (int i = 0; i < 4; i++) {
            int rg = m0 + rb + 32 * i;
            pa[i] = (rg < NN) ? S4[(size_t)rg * 32 + q] : make_float4(0.f, 0.f, 0.f, 0.f);
        }
        uint32_t dBH = sb + 2 * PLANE, dBL = sb + 3 * PLANE;
        CP_ASYNC16(dBH + n0 * BSTR + p0 * 16, BhC + n0 * 768 + p0 * 16);
        CP_ASYNC16(dBH + n1 * BSTR + p1 * 16, BhC + n1 * 768 + p1 * 16);
        CP_ASYNC16(dBL + n0 * BSTR + p0 * 16, BlC + n0 * 768 + p0 * 16);
        CP_ASYNC16(dBL + n1 * BSTR + p1 * 16, BlC + n1 * 768 + p1 * 16);
        CP_COMMIT();
#pragma unroll
        for (int i = 0; i < 4; i++) {
            float4 v = pa[i];
            __nv_bfloat162 h01 = __floats2bfloat162_rn(v.x, v.y);
            __nv_bfloat162 h23 = __floats2bfloat162_rn(v.z, v.w);
            __nv_bfloat162 l01 = __floats2bfloat162_rn(v.x - __bfloat162float(h01.x),
                                                       v.y - __bfloat162float(h01.y));
            __nv_bfloat162 l23 = __floats2bfloat162_rn(v.z - __bfloat162float(h23.x),
                                                       v.w - __bfloat162float(h23.y));
            int off = (rb + 32 * i) * BSTR + q * 8;
            *(__nv_bfloat162*)(smc + off)             = h01;
            *(__nv_bfloat162*)(smc + off + 4)         = h23;
            *(__nv_bfloat162*)(smc + PLANE + off)     = l01;
            *(__nv_bfloat162*)(smc + PLANE + off + 4) = l23;
        }
        CP_WAIT0();
        __syncthreads();
    }

    for (int ch = 0; ch < 12; ch++) {
        int s = ch & 1;
        int have_next = (ch + 1 < 12);
        if (have_next) {
            int nc = ch + 1;
            const float4* S4 = (const float4*)srcs[nc >> 2];
            int k4off = (nc & 3) * 8;
#pragma unroll
            for (int i = 0; i < 4; i++) {
                int rg = m0 + rb + 32 * i;
                pa[i] = (rg < NN) ? S4[(size_t)rg * 32 + k4off + q]
                                  : make_float4(0.f, 0.f, 0.f, 0.f);
            }
            uint32_t st = sb + (1 - s) * STAGE;
            uint32_t dBH = st + 2 * PLANE, dBL = st + 3 * PLANE;
            int gk = nc * 64;
            CP_ASYNC16(dBH + n0 * BSTR + p0 * 16, BhC + n0 * 768 + gk + p0 * 16);
            CP_ASYNC16(dBH + n1 * BSTR + p1 * 16, BhC + n1 * 768 + gk + p1 * 16);
            CP_ASYNC16(dBL + n0 * BSTR + p0 * 16, BlC + n0 * 768 + gk + p0 * 16);
            CP_ASYNC16(dBL + n1 * BSTR + p1 * 16, BlC + n1 * 768 + gk + p1 * 16);
            CP_COMMIT();
        }

        uint32_t st = sb + s * STAGE;
        uint32_t aAH = st, aAL = st + PLANE, aBH = st + 2 * PLANE, aBL = st + 3 * PLANE;
#pragma unroll
        for (int ks = 0; ks < 2; ks++) {
            uint32_t ah[2][4], al[2][4], bh[8][2], bl[8][2];
            uint32_t aoff = (uint32_t)((wm + (lane & 15)) * BSTR
                          + ks * 32 + (lane >> 4) * 16);
            ldsm4(ah[0], aAH + aoff);
            ldsm4(ah[1], aAH + aoff + 16 * BSTR);
            ldsm4(al[0], aAL + aoff);
            ldsm4(al[1], aAL + aoff + 16 * BSTR);
            uint32_t boff = (uint32_t)((wn + ((lane >> 4) << 3) + (lane & 7)) * BSTR
                          + ks * 32 + ((lane >> 3) & 1) * 16);
#pragma unroll
            for (int p = 0; p < 4; p++) {
                uint32_t r4[4];
                ldsm4(r4, aBH + boff + p * 16 * BSTR);
                bh[2*p][0] = r4[0]; bh[2*p][1] = r4[1];
                bh[2*p+1][0] = r4[2]; bh[2*p+1][1] = r4[3];
                ldsm4(r4, aBL + boff + p * 16 * BSTR);
                bl[2*p][0] = r4[0]; bl[2*p][1] = r4[1];
                bl[2*p+1][0] = r4[2]; bl[2*p+1][1] = r4[3];
            }
#pragma unroll
            for (int mi = 0; mi < 2; mi++)
#pragma unroll
                for (int nj = 0; nj < 8; nj++) {
                    mma16816(acc[mi][nj], ah[mi], bh[nj]);
                    mma16816(acc[mi][nj], ah[mi], bl[nj]);
                    mma16816(acc[mi][nj], al[mi], bh[nj]);
                }
        }

        if (have_next) {
            char* stc = smc + (1 - s) * STAGE;
#pragma unroll
            for (int i = 0; i < 4; i++) {
                float4 v = pa[i];
                __nv_bfloat162 h01 = __floats2bfloat162_rn(v.x, v.y);
                __nv_bfloat162 h23 = __floats2bfloat162_rn(v.z, v.w);
                __nv_bfloat162 l01 = __floats2bfloat162_rn(v.x - __bfloat162float(h01.x),
                                                           v.y - __bfloat162float(h01.y));
                __nv_bfloat162 l23 = __floats2bfloat162_rn(v.z - __bfloat162float(h23.x),
                                                           v.w - __bfloat162float(h23.y));
                int off = (rb + 32 * i) * BSTR + q * 8;
                *(__nv_bfloat162*)(stc + off)             = h01;
                *(__nv_bfloat162*)(stc + off + 4)         = h23;
                *(__nv_bfloat162*)(stc + PLANE + off)     = l01;
                *(__nv_bfloat162*)(stc + PLANE + off + 4) = l23;
            }
            CP_WAIT0();
            __syncthreads();
        }
    }

#pragma unroll
    for (int mi = 0; mi < 2; mi++) {
        int r0 = m0 + wm + mi * 16 + (lane >> 2);
#pragma unroll
        for (int nj = 0; nj < 8; nj++) {
            int c = wn + nj * 8 + 2 * (lane & 3);
            float bx = __ldg(bias + c), by = __ldg(bias + c + 1);
            if (r0 < NN) {
                float2 o;
                o.x = fmaxf(acc[mi][nj][0] + bx, 0.f);
                o.y = fmaxf(acc[mi][nj][1] + by, 0.f);
                *(float2*)(out + (size_t)r0 * CC + c) = o;
            }
            if (r0 + 8 < NN) {
                float2 o;
                o.x = fmaxf(acc[mi][nj][2] + bx, 0.f);
                o.y = fmaxf(acc[mi][nj][3] + by, 0.f);
                *(float2*)(out + (size_t)(r0 + 8) * CC + c) = o;
            }
        }
    }
}

// fused tail: zero -> stats/pool/cnt -> bnprep -> mlp  (148 blocks x 128 threads)
__global__ void __launch_bounds__(128)
k_tail(const float* __restrict__ h, const int* __restrict__ batch,
       const float* __restrict__ gamma, const float* __restrict__ beta,
       const float* __restrict__ lw1, const float* __restrict__ lb1,
       const float* __restrict__ lw2, const float* __restrict__ lb2,
       float* __restrict__ out) {
    int tid = threadIdx.x, b = blockIdx.x;
    int gt = b * 128 + tid;
    const int GT = TLB * 128;

    // A: zero reduction buffers
    for (int i = gt; i < GG * CC; i += GT) g_pool[i] = 0.f;
    for (int i = gt; i < GG; i += GT) g_cnt[i] = 0.f;
    if (gt < CC) { g_chsum[gt] = 0.f; g_chsq[gt] = 0.f; }
    gridbar(&g_syncT[0], TLB);

    // B: stats + pool + cnt over 128-row tiles (batch sorted -> run accumulation)
    int c = tid;
    float s = 0.f, sq = 0.f;
    for (int t = b; t < NTILE; t += TLB) {
        int base = t * 128;
        float acc = 0.f, cacc = 0.f;
        int cur = -1;
        for (int r = 0; r < 128; r++) {
            int n = base + r;
            if (n >= NN) break;
            int g = batch[n];
            float v = h[(size_t)n * CC + c];
            s += v;
            sq += v * v;
            if (g != cur) {
                if (cur >= 0) {
                    atomicAdd(&g_pool[cur * CC + c], acc);
                    if (c == 0) atomicAdd(&g_cnt[cur], cacc);
                }
                cur = g;
                acc = 0.f;
                cacc = 0.f;
            }
            acc += v;
            cacc += 1.f;
        }
        if (cur >= 0) {
            atomicAdd(&g_pool[cur * CC + c], acc);
            if (c == 0) atomicAdd(&g_cnt[cur], cacc);
        }
    }
    atomicAdd(&g_chsum[c], s);
    atomicAdd(&g_chsq[c], sq);
    gridbar(&g_syncT[1], TLB);

    // C: BN fold (block 0)
    if (b == 0) {
        float mu = g_chsum[c] * (1.0f / NN);
        float var = fmaxf(g_chsq[c] * (1.0f / NN) - mu * mu, 0.f);
        float inv = rsqrtf(var + 1e-5f);
        float a = gamma[c] * inv;
        g_bna[c] = a;
        g_bnb[c] = beta[c] - mu * a;
    }
    gridbar(&g_syncT[2], TLB);

    // D: head MLP (one thread per graph; blocks 0-3 cover 512)
    int g = gt;
    if (g < GG) {
        float inv = 1.0f / fmaxf(g_cnt[g], 1.0f);
        float hid[16];
#pragma unroll
        for (int j = 0; j < 16; j++) hid[j] = lb1[j];
#pragma unroll 4
        for (int cc2 = 0; cc2 < CC; cc2++) {
            float pb = g_pool[g * CC + cc2] * inv * g_bna[cc2] + g_bnb[cc2];
            const float4* w4 = (const float4*)(lw1 + cc2 * 16);
#pragma unroll
            for (int qq = 0; qq < 4; qq++) {
                float4 w = w4[qq];
                hid[qq * 4 + 0] += pb * w.x;
                hid[qq * 4 + 1] += pb * w.y;
                hid[qq * 4 + 2] += pb * w.z;
                hid[qq * 4 + 3] += pb * w.w;
            }
        }
        float o0 = lb2[0], o1 = lb2[1];
#pragma unroll
        for (int j = 0; j < 16; j++) {
            float r = fmaxf(hid[j], 0.f);
            o0 += r * lw2[j * 2 + 0];
            o1 += r * lw2[j * 2 + 1];
        }
        out[g * 2 + 0] = o0;
        out[g * 2 + 1] = o1;
    }
    gridexit(&g_syncT[3], g_syncT, 8, TLB, b);
}

// ---------------- launcher ----------------
extern "C" void kernel_launch(void* const* d_in, const int* in_sizes, int n_in,
                              void* d_out, int out_size) {
    const float* atom_emb = (const float*)d_in[0];
    const float* W1   = (const float*)d_in[1];
    const float* b1   = (const float*)d_in[2];
    const float* W3   = (const float*)d_in[3];
    const float* b3   = (const float*)d_in[4];
    const float* gam  = (const float*)d_in[5];
    const float* bet  = (const float*)d_in[6];
    const float* lw1  = (const float*)d_in[7];
    const float* lb1  = (const float*)d_in[8];
    const float* lw2  = (const float*)d_in[9];
    const float* lb2  = (const float*)d_in[10];
    const int*   x    = (const int*)d_in[11];
    const int*   ei   = (const int*)d_in[12];
    const int*   batch= (const int*)d_in[13];
    const int* row = ei;
    const int* col = ei + EE;
    float* out = (float*)d_out;

    float *h0, *h1, *t1, *t2;
    __nv_bfloat16 *Bh, *Bl;
    cudaGetSymbolAddress((void**)&h0, g_h0);
    cudaGetSymbolAddress((void**)&h1, g_h1);
    cudaGetSymbolAddress((void**)&t1, g_t1);
    cudaGetSymbolAddress((void**)&t2, g_t2);
    cudaGetSymbolAddress((void**)&Bh, g_Bh);
    cudaGetSymbolAddress((void**)&Bl, g_Bl);

    const int GEMM_SMEM = 2 * STAGE;   // 81920 B, 2 CTAs/SM
    cudaFuncSetAttribute(k_gemm, cudaFuncAttributeMaxDynamicSharedMemorySize, GEMM_SMEM);

    const int MM_B = (NN + 127) / 128;          // 391 tiles

    // (1) CSR build + embedding + both weight folds
    k_csr<<<CSRB, 256>>>(row, col, atom_emb, x, W1, W3);

    // (2) conv1 double SpMV + (3) GEMM
    k_spmv2<<<SPB, 256>>>(h0, t1, t2);
    k_gemm<<<MM_B, 256, GEMM_SMEM>>>(h0, t1, t2, Bh, Bl, b1, h1);

    // (4) conv2 double SpMV + (5) GEMM (conv3 weights), writes into h0
    k_spmv2<<<SPB, 256>>>(h1, t1, t2);
    k_gemm<<<MM_B, 256, GEMM_SMEM>>>(h1, t1, t2, Bh + (size_t)CC * 384,
                                     Bl + (size_t)CC * 384, b3, h0);

    // (6) fused tail: zero + stats/pool/cnt + bnprep + mlp
    k_tail<<<TLB, 128>>>(h0, batch, gam, bet, lw1, lb1, lw2, lb2, out);
}

// round 15
// speedup vs baseline: 1.1875x; 1.1875x over previous
#include <cuda_runtime.h>
#include <cuda_bf16.h>
#include <cstdint>

#define NN 50000
#define EE 800000
#define GG 512
#define CC 128
#define NBLK 196          // ceil(NN/256) node tiles
#define CSRB 148          // CSR builder blocks (1/SM, co-resident)
#define SPB  592          // SpMV blocks (4/SM, co-resident)

// ---------------- scratch (static device arrays; no allocation) ----------------
__device__ float g_h0[NN*CC];
__device__ float g_h1[NN*CC];
__device__ float g_t1[NN*CC];
__device__ float g_t2[NN*CC];
__device__ float g_dis[NN];
__device__ int   g_hist[NN];
__device__ int   g_ptr[NN+1];
__device__ int   g_fill[NN];
__device__ int   g_bsum[NBLK];
__device__ int   g_syncC[8];         // csr barrier counters (self-reset)
__device__ int   g_syncS[4];         // spmv2 barrier counters (self-reset)
__device__ int2  g_epk[EE];          // packed CSR: (col, bits(norm))
__device__ float g_pool[GG*CC];
__device__ float g_cnt[GG];
__device__ float g_chsum[CC];
__device__ float g_chsq[CC];
__device__ float g_bna[CC];
__device__ float g_bnb[CC];
// split-bf16 weights for BOTH convs: [conv][n*384+k] (transposed, folded)
__device__ __align__(16) __nv_bfloat16 g_Bh[2][CC*384];
__device__ __align__(16) __nv_bfloat16 g_Bl[2][CC*384];

// ---------------- mma.sync helpers (baseline PTX, works at compute_103) --------
__device__ __forceinline__ void ldsm4(uint32_t* r, uint32_t addr) {
    asm volatile("ldmatrix.sync.aligned.m8n8.x4.shared.b16 {%0,%1,%2,%3}, [%4];"
                 : "=r"(r[0]), "=r"(r[1]), "=r"(r[2]), "=r"(r[3]) : "r"(addr));
}
__device__ __forceinline__ void mma16816(float* c, const uint32_t* a, const uint32_t* b) {
    asm volatile("mma.sync.aligned.m16n8k16.row.col.f32.bf16.bf16.f32 "
                 "{%0,%1,%2,%3}, {%4,%5,%6,%7}, {%8,%9}, {%0,%1,%2,%3};"
                 : "+f"(c[0]), "+f"(c[1]), "+f"(c[2]), "+f"(c[3])
                 : "r"(a[0]), "r"(a[1]), "r"(a[2]), "r"(a[3]), "r"(b[0]), "r"(b[1]));
}
__device__ __forceinline__ uint32_t smem_u32(const void* p) {
    uint32_t a;
    asm("{ .reg .u64 t; cvta.to.shared.u64 t, %1; cvt.u32.u64 %0, t; }" : "=r"(a) : "l"(p));
    return a;
}
#define CP_ASYNC16(dst, src) \
    asm volatile("cp.async.cg.shared.global [%0], [%1], 16;" \
                 :: "r"(dst), "l"(src) : "memory")
#define CP_COMMIT() asm volatile("cp.async.commit_group;" ::: "memory")
#define CP_WAIT0()  asm volatile("cp.async.wait_group 0;" ::: "memory")

// device-scope grid barrier for co-resident grids (all threads fence first)
__device__ __forceinline__ void gridbar(int* ctr, int nblk) {
    __threadfence();
    __syncthreads();
    if (threadIdx.x == 0) {
        atomicAdd(ctr, 1);
        while (atomicAdd(ctr, 0) < nblk) { }
    }
    __syncthreads();
}
// exit protocol: block 0 resets counters for graph replay
__device__ __forceinline__ void gridexit(int* ctr, int* arr, int na, int nblk, int b) {
    __threadfence();
    __syncthreads();
    if (threadIdx.x == 0) {
        atomicAdd(ctr, 1);
        if (b == 0) {
            while (atomicAdd(ctr, 0) < nblk) { }
            for (int i = 0; i < na; i++) arr[i] = 0;
            __threadfence();
        }
    }
}

// ---------------- small utility kernels ----------------
__global__ void k_zero4(float* __restrict__ p, int n4) {
    int i = blockIdx.x * blockDim.x + threadIdx.x;
    if (i < n4) ((float4*)p)[i] = make_float4(0.f, 0.f, 0.f, 0.f);
}

// ---------------- fused CSR build (R12/R13-proven; no embed/prep inside) -------
__global__ void __launch_bounds__(256)
k_csr(const int* __restrict__ row, const int* __restrict__ col) {
    __shared__ int sh[256];
    __shared__ int sb[256];
    int tid = threadIdx.x, b = blockIdx.x;
    int gt = b * 256 + tid;
    const int GT = CSRB * 256;

    for (int n = gt; n < NN; n += GT) g_hist[n] = 0;
    gridbar(&g_syncC[0], CSRB);

    for (int e = gt; e < EE; e += GT) atomicAdd(&g_hist[row[e]], 1);
    gridbar(&g_syncC[1], CSRB);

    for (int t = b; t < NBLK; t += CSRB) {
        int n = t * 256 + tid;
        int h = (n < NN) ? g_hist[n] : 0;
        if (n < NN) g_dis[n] = (h > 0) ? rsqrtf((float)h) : 0.f;
        sh[tid] = h;
        __syncthreads();
        for (int s = 128; s > 0; s >>= 1) {
            if (tid < s) sh[tid] += sh[tid + s];
            __syncthreads();
        }
        if (tid == 0) g_bsum[t] = sh[0];
        __syncthreads();
    }
    gridbar(&g_syncC[2], CSRB);

    int bv = (tid < NBLK) ? g_bsum[tid] : 0;
    sb[tid] = bv;
    __syncthreads();
    for (int o = 1; o < 256; o <<= 1) {
        int xx = (tid >= o) ? sb[tid - o] : 0;
        __syncthreads();
        sb[tid] += xx;
        __syncthreads();
    }
    for (int t = b; t < NBLK; t += CSRB) {
        int base = (t == 0) ? 0 : sb[t - 1];
        int n = t * 256 + tid;
        int v = (n < NN) ? g_hist[n] : 0;
        sh[tid] = v;
        __syncthreads();
        for (int o = 1; o < 256; o <<= 1) {
            int xx = (tid >= o) ? sh[tid - o] : 0;
            __syncthreads();
            sh[tid] += xx;
            __syncthreads();
        }
        int off = base + sh[tid] - v;
        if (n < NN) { g_ptr[n] = off; g_fill[n] = off; }
        if (n == NN - 1) g_ptr[NN] = off + v;
        __syncthreads();
    }
    gridbar(&g_syncC[3], CSRB);

    for (int e = gt; e < EE; e += GT) {
        int r = row[e], c = col[e];
        int pos = atomicAdd(&g_fill[r], 1);
        float w = -(g_dis[r] * g_dis[c]);
        g_epk[pos] = make_int2(c, __float_as_int(w));
    }
    gridexit(&g_syncC[4], g_syncC, 8, CSRB, b);
}

// SpMV row body (proven form; at LTS cap — do not touch)
__device__ __forceinline__ void spmv_row(const float* __restrict__ src,
                                         float* __restrict__ dst, int w, int lane) {
    int s = g_ptr[w], e = g_ptr[w + 1];
    float4 acc = make_float4(0.f, 0.f, 0.f, 0.f);
    for (int j = s; j < e; j += 32) {
        int idx = j + lane;
        int2 pk = (idx < e) ? g_epk[idx] : make_int2(0, 0);
        int cnt = min(32, e - j);
        for (int k = 0; k < cnt; k++) {
            int ck = __shfl_sync(0xffffffffu, pk.x, k);
            float wk = __uint_as_float(__shfl_sync(0xffffffffu, (unsigned)pk.y, k));
            float4 v = ((const float4*)(src + (size_t)ck * CC))[lane];
            acc.x = fmaf(wk, v.x, acc.x);
            acc.y = fmaf(wk, v.y, acc.y);
            acc.z = fmaf(wk, v.z, acc.z);
            acc.w = fmaf(wk, v.w, acc.w);
        }
    }
    ((float4*)(dst + (size_t)w * CC))[lane] = acc;
}

// fused double SpMV: t1 = L src; grid barrier; t2 = L t1  (persistent, 4 CTAs/SM)
// R14-measured WIN: 64.1us vs 73.3us for two separate launches
__global__ void __launch_bounds__(256, 4)
k_spmv2(const float* __restrict__ src, float* __restrict__ t1, float* __restrict__ t2) {
    int tid = threadIdx.x, b = blockIdx.x;
    int gw = (b * 256 + tid) >> 5;
    int lane = tid & 31;
    const int NW = SPB * 8;

    for (int w = gw; w < NN; w += NW) spmv_row(src, t1, w, lane);
    gridbar(&g_syncS[0], SPB);
    for (int w = gw; w < NN; w += NW) spmv_row(t1, t2, w, lane);
    gridexit(&g_syncS[1], g_syncS, 4, SPB, b);
}

// AtomEncoder: h0[n,c] = sum_f atom_emb[f, x[n,f], c]  (full-parallel, R13 form)
__global__ void k_embed(const float* __restrict__ emb, const int* __restrict__ x) {
    int n = blockIdx.x;
    __shared__ int xs[9];
    if (threadIdx.x < 9) xs[threadIdx.x] = x[n * 9 + threadIdx.x];
    __syncthreads();
    int c = threadIdx.x;
    float s = 0.f;
#pragma unroll
    for (int f = 0; f < 9; f++)
        s += emb[((f * 119) + xs[f]) * CC + c];
    g_h0[(size_t)n * CC + c] = s;
}

// Build folded, transposed, split-bf16 weights for BOTH convs in one launch.
__global__ void k_prepB2(const float* __restrict__ WA, const float* __restrict__ WB) {
    int which = blockIdx.x >> 7;
    int n = blockIdx.x & 127;
    int k = threadIdx.x;      // 0..383
    const float* W = which ? WB : WA;
    int blk = k >> 7, ci = k & 127;
    float w;
    if (blk == 0)      w = W[ci * 128 + n] - W[2 * 16384 + ci * 128 + n];
    else if (blk == 1) w = W[16384 + ci * 128 + n];
    else               w = 2.f * W[2 * 16384 + ci * 128 + n];
    __nv_bfloat16 hi = __float2bfloat16(w);
    g_Bh[which][n * 384 + k] = hi;
    g_Bl[which][n * 384 + k] = __float2bfloat16(w - __bfloat162float(hi));
}

// double-buffered mma.sync split-bf16 GEMM (byte-identical to R13's proven kernel)
#define BSTR 80
#define PLANE (128 * BSTR)
#define STAGE (4 * PLANE)
__global__ void __launch_bounds__(256, 2)
k_gemm(const float* __restrict__ A0, const float* __restrict__ A1,
       const float* __restrict__ A2, const __nv_bfloat16* __restrict__ Bh_,
       const __nv_bfloat16* __restrict__ Bl_, const float* __restrict__ bias,
       float* __restrict__ out)
{
    extern __shared__ char sm[];
    uint32_t sb = smem_u32(sm);
    char* smc = sm;

    int tid = threadIdx.x;
    int lane = tid & 31, wid = tid >> 5;
    int wm = (wid & 3) * 32;
    int wn = (wid >> 2) * 64;
    int m0 = blockIdx.x * 128;

    float acc[2][8][4];
#pragma unroll
    for (int mi = 0; mi < 2; mi++)
#pragma unroll
        for (int nj = 0; nj < 8; nj++)
#pragma unroll
            for (int q = 0; q < 4; q++) acc[mi][nj][q] = 0.f;

    const float* srcs[3] = {A0, A1, A2};
    const char* BhC = (const char*)Bh_;
    const char* BlC = (const char*)Bl_;

    int rb = tid >> 3;
    int q  = tid & 7;
    int n0 = tid >> 2,  p0 = tid & 3;
    int n1 = (tid + 256) >> 2, p1 = (tid + 256) & 3;

    float4 pa[4];

    {
        const float4* S4 = (const float4*)srcs[0];
#pragma unroll
        for (int i = 0; i < 4; i++) {
            int rg = m0 + rb + 32 * i;
            pa[i] = (rg < NN) ? S4[(size_t)rg * 32 + q] : make_float4(0.f, 0.f, 0.f, 0.f);
        }
        uint32_t dBH = sb + 2 * PLANE, dBL = sb + 3 * PLANE;
        CP_ASYNC16(dBH + n0 * BSTR + p0 * 16, BhC + n0 * 768 + p0 * 16);
        CP_ASYNC16(dBH + n1 * BSTR + p1 * 16, BhC + n1 * 768 + p1 * 16);
        CP_ASYNC16(dBL + n0 * BSTR + p0 * 16, BlC + n0 * 768 + p0 * 16);
        CP_ASYNC16(dBL + n1 * BSTR + p1 * 16, BlC + n1 * 768 + p1 * 16);
        CP_COMMIT();
#pragma unroll
        for (int i = 0; i < 4; i++) {
            float4 v = pa[i];
            __nv_bfloat162 h01 = __floats2bfloat162_rn(v.x, v.y);
            __nv_bfloat162 h23 = __floats2bfloat162_rn(v.z, v.w);
            __nv_bfloat162 l01 = __floats2bfloat162_rn(v.x - __bfloat162float(h01.x),
                                                       v.y - __bfloat162float(h01.y));
            __nv_bfloat162 l23 = __floats2bfloat162_rn(v.z - __bfloat162float(h23.x),
                                                       v.w - __bfloat162float(h23.y));
            int off = (rb + 32 * i) * BSTR + q * 8;
            *(__nv_bfloat162*)(smc + off)             = h01;
            *(__nv_bfloat162*)(smc + off + 4)         = h23;
            *(__nv_bfloat162*)(smc + PLANE + off)     = l01;
            *(__nv_bfloat162*)(smc + PLANE + off + 4) = l23;
        }
        CP_WAIT0();
        __syncthreads();
    }

    for (int ch = 0; ch < 12; ch++) {
        int s = ch & 1;
        int have_next = (ch + 1 < 12);
        if (have_next) {
            int nc = ch + 1;
            const float4* S4 = (const float4*)srcs[nc >> 2];
            int k4off = (nc & 3) * 8;
#pragma unroll
            for (int i = 0; i < 4; i++) {
                int rg = m0 + rb + 32 * i;
                pa[i] = (rg < NN) ? S4[(size_t)rg * 32 + k4off + q]
                                  : make_float4(0.f, 0.f, 0.f, 0.f);
            }
            uint32_t st = sb + (1 - s) * STAGE;
            uint32_t dBH = st + 2 * PLANE, dBL = st + 3 * PLANE;
            int gk = nc * 64;
            CP_ASYNC16(dBH + n0 * BSTR + p0 * 16, BhC + n0 * 768 + gk + p0 * 16);
            CP_ASYNC16(dBH + n1 * BSTR + p1 * 16, BhC + n1 * 768 + gk + p1 * 16);
            CP_ASYNC16(dBL + n0 * BSTR + p0 * 16, BlC + n0 * 768 + gk + p0 * 16);
            CP_ASYNC16(dBL + n1 * BSTR + p1 * 16, BlC + n1 * 768 + gk + p1 * 16);
            CP_COMMIT();
        }

        uint32_t st = sb + s * STAGE;
        uint32_t aAH = st, aAL = st + PLANE, aBH = st + 2 * PLANE, aBL = st + 3 * PLANE;
#pragma unroll
        for (int ks = 0; ks < 2; ks++) {
            uint32_t ah[2][4], al[2][4], bh[8][2], bl[8][2];
            uint32_t aoff = (uint32_t)((wm + (lane & 15)) * BSTR
                          + ks * 32 + (lane >> 4) * 16);
            ldsm4(ah[0], aAH + aoff);
            ldsm4(ah[1], aAH + aoff + 16 * BSTR);
            ldsm4(al[0], aAL + aoff);
            ldsm4(al[1], aAL + aoff + 16 * BSTR);
            uint32_t boff = (uint32_t)((wn + ((lane >> 4) << 3) + (lane & 7)) * BSTR
                          + ks * 32 + ((lane >> 3) & 1) * 16);
#pragma unroll
            for (int p = 0; p < 4; p++) {
                uint32_t r4[4];
                ldsm4(r4, aBH + boff + p * 16 * BSTR);
                bh[2*p][0] = r4[0]; bh[2*p][1] = r4[1];
                bh[2*p+1][0] = r4[2]; bh[2*p+1][1] = r4[3];
                ldsm4(r4, aBL + boff + p * 16 * BSTR);
                bl[2*p][0] = r4[0]; bl[2*p][1] = r4[1];
                bl[2*p+1][0] = r4[2]; bl[2*p+1][1] = r4[3];
            }
#pragma unroll
            for (int mi = 0; mi < 2; mi++)
#pragma unroll
                for (int nj = 0; nj < 8; nj++) {
                    mma16816(acc[mi][nj], ah[mi], bh[nj]);
                    mma16816(acc[mi][nj], ah[mi], bl[nj]);
                    mma16816(acc[mi][nj], al[mi], bh[nj]);
                }
        }

        if (have_next) {
            char* stc = smc + (1 - s) * STAGE;
#pragma unroll
            for (int i = 0; i < 4; i++) {
                float4 v = pa[i];
                __nv_bfloat162 h01 = __floats2bfloat162_rn(v.x, v.y);
                __nv_bfloat162 h23 = __floats2bfloat162_rn(v.z, v.w);
                __nv_bfloat162 l01 = __floats2bfloat162_rn(v.x - __bfloat162float(h01.x),
                                                           v.y - __bfloat162float(h01.y));
                __nv_bfloat162 l23 = __floats2bfloat162_rn(v.z - __bfloat162float(h23.x),
                                                           v.w - __bfloat162float(h23.y));
                int off = (rb + 32 * i) * BSTR + q * 8;
                *(__nv_bfloat162*)(stc + off)             = h01;
                *(__nv_bfloat162*)(stc + off + 4)         = h23;
                *(__nv_bfloat162*)(stc + PLANE + off)     = l01;
                *(__nv_bfloat162*)(stc + PLANE + off + 4) = l23;
            }
            CP_WAIT0();
            __syncthreads();
        }
    }

#pragma unroll
    for (int mi = 0; mi < 2; mi++) {
        int r0 = m0 + wm + mi * 16 + (lane >> 2);
#pragma unroll
        for (int nj = 0; nj < 8; nj++) {
            int c = wn + nj * 8 + 2 * (lane & 3);
            float bx = __ldg(bias + c), by = __ldg(bias + c + 1);
            if (r0 < NN) {
                float2 o;
                o.x = fmaxf(acc[mi][nj][0] + bx, 0.f);
                o.y = fmaxf(acc[mi][nj][1] + by, 0.f);
                *(float2*)(out + (size_t)r0 * CC + c) = o;
            }
            if (r0 + 8 < NN) {
                float2 o;
                o.x = fmaxf(acc[mi][nj][2] + bx, 0.f);
                o.y = fmaxf(acc[mi][nj][3] + by, 0.f);
                *(float2*)(out + (size_t)(r0 + 8) * CC + c) = o;
            }
        }
    }
}

// per-graph node counts
__global__ void k_cnt(const int* __restrict__ batch) {
    int n = blockIdx.x * blockDim.x + threadIdx.x;
    if (n < NN) atomicAdd(&g_cnt[batch[n]], 1.0f);
}

// channel sums/sumsq (for BN) + per-graph pooling sums (batch sorted -> run accumulation)
__global__ void k_statspool(const float* __restrict__ h, const int* __restrict__ batch) {
    int c = threadIdx.x;
    int base = blockIdx.x * 128;
    float s = 0.f, sq = 0.f, acc = 0.f;
    int cur = -1;
    for (int r = 0; r < 128; r++) {
        int n = base + r;
        if (n >= NN) break;
        int g = batch[n];
        float v = h[(size_t)n * CC + c];
        s += v;
        sq += v * v;
        if (g != cur) {
            if (cur >= 0) atomicAdd(&g_pool[cur * CC + c], acc);
            cur = g;
            acc = 0.f;
        }
        acc += v;
    }
    if (cur >= 0) atomicAdd(&g_pool[cur * CC + c], acc);
    atomicAdd(&g_chsum[c], s);
    atomicAdd(&g_chsq[c], sq);
}

__global__ void k_bnprep(const float* __restrict__ gamma, const float* __restrict__ beta) {
    int c = threadIdx.x;
    float mu = g_chsum[c] * (1.0f / NN);
    float var = fmaxf(g_chsq[c] * (1.0f / NN) - mu * mu, 0.f);
    float inv = rsqrtf(var + 1e-5f);
    float a = gamma[c] * inv;
    g_bna[c] = a;
    g_bnb[c] = beta[c] - mu * a;
}

__global__ void k_mlp(const float* __restrict__ lw1, const float* __restrict__ lb1,
                      const float* __restrict__ lw2, const float* __restrict__ lb2,
                      float* __restrict__ out) {
    int g = blockIdx.x * blockDim.x + threadIdx.x;
    if (g >= GG) return;
    float inv = 1.0f / fmaxf(g_cnt[g], 1.0f);
    float hid[16];
#pragma unroll
    for (int j = 0; j < 16; j++) hid[j] = lb1[j];
#pragma unroll 4
    for (int c = 0; c < CC; c++) {
        float pb = g_pool[g * CC + c] * inv * g_bna[c] + g_bnb[c];
        const float4* w4 = (const float4*)(lw1 + c * 16);
#pragma unroll
        for (int qq = 0; qq < 4; qq++) {
            float4 w = w4[qq];
            hid[qq * 4 + 0] += pb * w.x;
            hid[qq * 4 + 1] += pb * w.y;
            hid[qq * 4 + 2] += pb * w.z;
            hid[qq * 4 + 3] += pb * w.w;
        }
    }
    float o0 = lb2[0], o1 = lb2[1];
#pragma unroll
    for (int j = 0; j < 16; j++) {
        float r = fmaxf(hid[j], 0.f);
        o0 += r * lw2[j * 2 + 0];
        o1 += r * lw2[j * 2 + 1];
    }
    out[g * 2 + 0] = o0;
    out[g * 2 + 1] = o1;
}

// ---------------- launcher ----------------
extern "C" void kernel_launch(void* const* d_in, const int* in_sizes, int n_in,
                              void* d_out, int out_size) {
    const float* atom_emb = (const float*)d_in[0];
    const float* W1   = (const float*)d_in[1];
    const float* b1   = (const float*)d_in[2];
    const float* W3   = (const float*)d_in[3];
    const float* b3   = (const float*)d_in[4];
    const float* gam  = (const float*)d_in[5];
    const float* bet  = (const float*)d_in[6];
    const float* lw1  = (const float*)d_in[7];
    const float* lb1  = (const float*)d_in[8];
    const float* lw2  = (const float*)d_in[9];
    const float* lb2  = (const float*)d_in[10];
    const int*   x    = (const int*)d_in[11];
    const int*   ei   = (const int*)d_in[12];
    const int*   batch= (const int*)d_in[13];
    const int* row = ei;
    const int* col = ei + EE;
    float* out = (float*)d_out;

    float *h0, *h1, *t1, *t2, *pool, *cnt, *chsum, *chsq;
    __nv_bfloat16 *Bh, *Bl;
    cudaGetSymbolAddress((void**)&h0, g_h0);
    cudaGetSymbolAddress((void**)&h1, g_h1);
    cudaGetSymbolAddress((void**)&t1, g_t1);
    cudaGetSymbolAddress((void**)&t2, g_t2);
    cudaGetSymbolAddress((void**)&pool, g_pool);
    cudaGetSymbolAddress((void**)&cnt, g_cnt);
    cudaGetSymbolAddress((void**)&chsum, g_chsum);
    cudaGetSymbolAddress((void**)&chsq, g_chsq);
    cudaGetSymbolAddress((void**)&Bh, g_Bh);
    cudaGetSymbolAddress((void**)&Bl, g_Bl);

    const int GEMM_SMEM = 2 * STAGE;   // 81920 B, 2 CTAs/SM
    cudaFuncSetAttribute(k_gemm, cudaFuncAttributeMaxDynamicSharedMemorySize, GEMM_SMEM);

    const int NB = (NN + 255) / 256;
    const int MM_B = (NN + 127) / 128;          // 391 tiles

    // CSR build + embedding + both weight folds (R13-proven split)
    k_csr<<<CSRB, 256>>>(row, col);
    k_embed<<<NN, 128>>>(atom_emb, x);
    k_prepB2<<<256, 384>>>(W1, W3);

    // conv1: fused double SpMV + GEMM
    k_spmv2<<<SPB, 256>>>(h0, t1, t2);
    k_gemm<<<MM_B, 256, GEMM_SMEM>>>(h0, t1, t2, Bh, Bl, b1, h1);

    // conv2: fused double SpMV + GEMM (conv3 weights), writes into h0
    k_spmv2<<<SPB, 256>>>(h1, t1, t2);
    k_gemm<<<MM_B, 256, GEMM_SMEM>>>(h1, t1, t2, Bh + (size_t)CC * 384,
                                     Bl + (size_t)CC * 384, b3, h0);

    // BN stats + pooling (R13-proven tail); BN affine applied post-pool
    k_zero4<<<(GG * CC / 4 + 255) / 256, 256>>>(pool, GG * CC / 4);
    k_zero4<<<1, 128>>>(cnt, GG / 4);
    k_zero4<<<1, 32>>>(chsum, CC / 4);
    k_zero4<<<1, 32>>>(chsq, CC / 4);
    k_cnt<<<NB, 256>>>(batch);
    k_statspool<<<(NN + 127) / 128, 128>>>(h0, batch);
    k_bnprep<<<1, 128>>>(gam, bet);

    // head MLP
    k_mlp<<<2, 256>>>(lw1, lb1, lw2, lb2, out);
}

// round 16
// speedup vs baseline: 1.2126x; 1.0211x over previous
#include <cuda_runtime.h>
#include <cuda_bf16.h>
#include <cstdint>

#define NN 50000
#define EE 800000
#define GG 512
#define CC 128
#define NBLK 196          // ceil(NN/256) node tiles
#define CSRB 148          // CSR builder blocks (1/SM, co-resident)
#define SPB  592          // SpMV blocks (4/SM, co-resident)
#define TLB2 391          // tail blocks (matches statspool tiling; ~3/SM)
#define NTILE 391         // ceil(NN/128) stat tiles

// ---------------- scratch (static device arrays; no allocation) ----------------
__device__ float g_h0[NN*CC];
__device__ float g_h1[NN*CC];
__device__ float g_t1[NN*CC];
__device__ float g_t2[NN*CC];
__device__ float g_dis[NN];
__device__ int   g_hist[NN];
__device__ int   g_ptr[NN+1];
__device__ int   g_fill[NN];
__device__ int   g_bsum[NBLK];
__device__ int   g_syncC[8];         // csr barrier counters (self-reset)
__device__ int   g_syncS[8];         // spmv2 barrier counters (self-reset)
__device__ int   g_syncT[8];         // tail barrier counters (self-reset)
__device__ int2  g_epk[EE];          // packed CSR: (col, bits(norm))
__device__ float g_pool[GG*CC];
__device__ float g_cnt[GG];
__device__ float g_chsum[CC];
__device__ float g_chsq[CC];
__device__ float g_bna[CC];
__device__ float g_bnb[CC];
// split-bf16 weights for BOTH convs: [conv][n*384+k] (transposed, folded)
__device__ __align__(16) __nv_bfloat16 g_Bh[2][CC*384];
__device__ __align__(16) __nv_bfloat16 g_Bl[2][CC*384];

// ---------------- mma.sync helpers (baseline PTX, works at compute_103) --------
__device__ __forceinline__ void ldsm4(uint32_t* r, uint32_t addr) {
    asm volatile("ldmatrix.sync.aligned.m8n8.x4.shared.b16 {%0,%1,%2,%3}, [%4];"
                 : "=r"(r[0]), "=r"(r[1]), "=r"(r[2]), "=r"(r[3]) : "r"(addr));
}
__device__ __forceinline__ void mma16816(float* c, const uint32_t* a, const uint32_t* b) {
    asm volatile("mma.sync.aligned.m16n8k16.row.col.f32.bf16.bf16.f32 "
                 "{%0,%1,%2,%3}, {%4,%5,%6,%7}, {%8,%9}, {%0,%1,%2,%3};"
                 : "+f"(c[0]), "+f"(c[1]), "+f"(c[2]), "+f"(c[3])
                 : "r"(a[0]), "r"(a[1]), "r"(a[2]), "r"(a[3]), "r"(b[0]), "r"(b[1]));
}
__device__ __forceinline__ uint32_t smem_u32(const void* p) {
    uint32_t a;
    asm("{ .reg .u64 t; cvta.to.shared.u64 t, %1; cvt.u32.u64 %0, t; }" : "=r"(a) : "l"(p));
    return a;
}
#define CP_ASYNC16(dst, src) \
    asm volatile("cp.async.cg.shared.global [%0], [%1], 16;" \
                 :: "r"(dst), "l"(src) : "memory")
#define CP_COMMIT() asm volatile("cp.async.commit_group;" ::: "memory")
#define CP_WAIT0()  asm volatile("cp.async.wait_group 0;" ::: "memory")

// device-scope grid barrier for co-resident grids (all threads fence first)
__device__ __forceinline__ void gridbar(int* ctr, int nblk) {
    __threadfence();
    __syncthreads();
    if (threadIdx.x == 0) {
        atomicAdd(ctr, 1);
        while (atomicAdd(ctr, 0) < nblk) { }
    }
    __syncthreads();
}
// exit protocol: block 0 resets counters for graph replay
__device__ __forceinline__ void gridexit(int* ctr, int* arr, int na, int nblk, int b) {
    __threadfence();
    __syncthreads();
    if (threadIdx.x == 0) {
        atomicAdd(ctr, 1);
        if (b == 0) {
            while (atomicAdd(ctr, 0) < nblk) { }
            for (int i = 0; i < na; i++) arr[i] = 0;
            __threadfence();
        }
    }
}

// ---------------- fused CSR build + weight folds ----------------
__global__ void __launch_bounds__(256)
k_csr(const int* __restrict__ row, const int* __restrict__ col,
      const float* __restrict__ WA, const float* __restrict__ WB) {
    __shared__ int sh[256];
    __shared__ int sb[256];
    int tid = threadIdx.x, b = blockIdx.x;
    int gt = b * 256 + tid;
    const int GT = CSRB * 256;

    // E1: fold both convs' weights -> split-bf16, transposed (independent phase)
    for (int i = gt; i < 2 * CC * 384; i += GT) {
        int which = i / (CC * 384);
        int rem = i - which * (CC * 384);
        int n = rem / 384, k = rem - n * 384;
        const float* W = which ? WB : WA;
        int blk = k >> 7, ci = k & 127;
        float w;
        if (blk == 0)      w = W[ci * 128 + n] - W[2 * 16384 + ci * 128 + n];
        else if (blk == 1) w = W[16384 + ci * 128 + n];
        else               w = 2.f * W[2 * 16384 + ci * 128 + n];
        __nv_bfloat16 hi = __float2bfloat16(w);
        g_Bh[which][n * 384 + k] = hi;
        g_Bl[which][n * 384 + k] = __float2bfloat16(w - __bfloat162float(hi));
    }
    // P0: zero histogram
    for (int n = gt; n < NN; n += GT) g_hist[n] = 0;
    gridbar(&g_syncC[0], CSRB);

    // P1: degree histogram
    for (int e = gt; e < EE; e += GT) atomicAdd(&g_hist[row[e]], 1);
    gridbar(&g_syncC[1], CSRB);

    // P2: per-node dis + per-tile sums
    for (int t = b; t < NBLK; t += CSRB) {
        int n = t * 256 + tid;
        int h = (n < NN) ? g_hist[n] : 0;
        if (n < NN) g_dis[n] = (h > 0) ? rsqrtf((float)h) : 0.f;
        sh[tid] = h;
        __syncthreads();
        for (int s = 128; s > 0; s >>= 1) {
            if (tid < s) sh[tid] += sh[tid + s];
            __syncthreads();
        }
        if (tid == 0) g_bsum[t] = sh[0];
        __syncthreads();
    }
    gridbar(&g_syncC[2], CSRB);

    // P3: offsets — every block redundantly scans tile sums, then local scans
    int bv = (tid < NBLK) ? g_bsum[tid] : 0;
    sb[tid] = bv;
    __syncthreads();
    for (int o = 1; o < 256; o <<= 1) {
        int xx = (tid >= o) ? sb[tid - o] : 0;
        __syncthreads();
        sb[tid] += xx;
        __syncthreads();
    }
    for (int t = b; t < NBLK; t += CSRB) {
        int base = (t == 0) ? 0 : sb[t - 1];
        int n = t * 256 + tid;
        int v = (n < NN) ? g_hist[n] : 0;
        sh[tid] = v;
        __syncthreads();
        for (int o = 1; o < 256; o <<= 1) {
            int xx = (tid >= o) ? sh[tid - o] : 0;
            __syncthreads();
            sh[tid] += xx;
            __syncthreads();
        }
        int off = base + sh[tid] - v;
        if (n < NN) { g_ptr[n] = off; g_fill[n] = off; }
        if (n == NN - 1) g_ptr[NN] = off + v;
        __syncthreads();
    }
    gridbar(&g_syncC[3], CSRB);

    // P4: scatter packed (col, norm)
    for (int e = gt; e < EE; e += GT) {
        int r = row[e], c = col[e];
        int pos = atomicAdd(&g_fill[r], 1);
        float w = -(g_dis[r] * g_dis[c]);
        g_epk[pos] = make_int2(c, __float_as_int(w));
    }
    gridexit(&g_syncC[4], g_syncC, 8, CSRB, b);
}

// SpMV row body (proven form; at LTS cap — do not touch)
__device__ __forceinline__ void spmv_row(const float* __restrict__ src,
                                         float* __restrict__ dst, int w, int lane) {
    int s = g_ptr[w], e = g_ptr[w + 1];
    float4 acc = make_float4(0.f, 0.f, 0.f, 0.f);
    for (int j = s; j < e; j += 32) {
        int idx = j + lane;
        int2 pk = (idx < e) ? g_epk[idx] : make_int2(0, 0);
        int cnt = min(32, e - j);
        for (int k = 0; k < cnt; k++) {
            int ck = __shfl_sync(0xffffffffu, pk.x, k);
            float wk = __uint_as_float(__shfl_sync(0xffffffffu, (unsigned)pk.y, k));
            float4 v = ((const float4*)(src + (size_t)ck * CC))[lane];
            acc.x = fmaf(wk, v.x, acc.x);
            acc.y = fmaf(wk, v.y, acc.y);
            acc.z = fmaf(wk, v.z, acc.z);
            acc.w = fmaf(wk, v.w, acc.w);
        }
    }
    ((float4*)(dst + (size_t)w * CC))[lane] = acc;
}

// fused [optional embed] + double SpMV (persistent, 4 CTAs/SM; R14-measured WIN)
__global__ void __launch_bounds__(256, 4)
k_spmv2(const float* __restrict__ src, float* __restrict__ t1, float* __restrict__ t2,
        const float* __restrict__ emb, const int* __restrict__ x, int do_embed) {
    int tid = threadIdx.x, b = blockIdx.x;
    int gw = (b * 256 + tid) >> 5;
    int lane = tid & 31;
    const int NW = SPB * 8;

    if (do_embed) {
        // embed pre-phase (warp per node): h0[n,:] = sum_f emb[f, x[n,f], :]
        for (int n = gw; n < NN; n += NW) {
            int xf = (lane < 9) ? x[n * 9 + lane] : 0;
            float4 s = make_float4(0.f, 0.f, 0.f, 0.f);
#pragma unroll
            for (int f = 0; f < 9; f++) {
                int xv = __shfl_sync(0xffffffffu, xf, f);
                float4 e = ((const float4*)(emb + (size_t)((f * 119) + xv) * CC))[lane];
                s.x += e.x; s.y += e.y; s.z += e.z; s.w += e.w;
            }
            ((float4*)(g_h0 + (size_t)n * CC))[lane] = s;
        }
        gridbar(&g_syncS[0], SPB);
    }

    for (int w = gw; w < NN; w += NW) spmv_row(src, t1, w, lane);
    gridbar(&g_syncS[1], SPB);
    for (int w = gw; w < NN; w += NW) spmv_row(t1, t2, w, lane);
    gridexit(&g_syncS[2], g_syncS, 8, SPB, b);
}

// double-buffered mma.sync split-bf16 GEMM (byte-identical to R13/R15 proven kernel)
#define BSTR 80
#define PLANE (128 * BSTR)
#define STAGE (4 * PLANE)
__global__ void __launch_bounds__(256, 2)
k_gemm(const float* __restrict__ A0, const float* __restrict__ A1,
       const float* __restrict__ A2, const __nv_bfloat16* __restrict__ Bh_,
       const __nv_bfloat16* __restrict__ Bl_, const float* __restrict__ bias,
       float* __restrict__ out)
{
    extern __shared__ char sm[];
    uint32_t sb = smem_u32(sm);
    char* smc = sm;

    int tid = threadIdx.x;
    int lane = tid & 31, wid = tid >> 5;
    int wm = (wid & 3) * 32;
    int wn = (wid >> 2) * 64;
    int m0 = blockIdx.x * 128;

    float acc[2][8][4];
#pragma unroll
    for (int mi = 0; mi < 2; mi++)
#pragma unroll
        for (int nj = 0; nj < 8; nj++)
#pragma unroll
            for (int q = 0; q < 4; q++) acc[mi][nj][q] = 0.f;

    const float* srcs[3] = {A0, A1, A2};
    const char* BhC = (const char*)Bh_;
    const char* BlC = (const char*)Bl_;

    int rb = tid >> 3;
    int q  = tid & 7;
    int n0 = tid >> 2,  p0 = tid & 3;
    int n1 = (tid + 256) >> 2, p1 = (tid + 256) & 3;

    float4 pa[4];

    {
        const float4* S4 = (const float4*)srcs[0];
#pragma unroll
        for (int i = 0; i < 4; i++) {
            int rg = m0 + rb + 32 * i;
            pa[i] = (rg < NN) ? S4[(size_t)rg * 32 + q] : make_float4(0.f, 0.f, 0.f, 0.f);
        }
        uint32_t dBH = sb + 2 * PLANE, dBL = sb + 3 * PLANE;
        CP_ASYNC16(dBH + n0 * BSTR + p0 * 16, BhC + n0 * 768 + p0 * 16);
        CP_ASYNC16(dBH + n1 * BSTR + p1 * 16, BhC + n1 * 768 + p1 * 16);
        CP_ASYNC16(dBL + n0 * BSTR + p0 * 16, BlC + n0 * 768 + p0 * 16);
        CP_ASYNC16(dBL + n1 * BSTR + p1 * 16, BlC + n1 * 768 + p1 * 16);
        CP_COMMIT();
#pragma unroll
        for (int i = 0; i < 4; i++) {
            float4 v = pa[i];
            __nv_bfloat162 h01 = __floats2bfloat162_rn(v.x, v.y);
            __nv_bfloat162 h23 = __floats2bfloat162_rn(v.z, v.w);
            __nv_bfloat162 l01 = __floats2bfloat162_rn(v.x - __bfloat162float(h01.x),
                                                       v.y - __bfloat162float(h01.y));
            __nv_bfloat162 l23 = __floats2bfloat162_rn(v.z - __bfloat162float(h23.x),
                                                       v.w - __bfloat162float(h23.y));
            int off = (rb + 32 * i) * BSTR + q * 8;
            *(__nv_bfloat162*)(smc + off)             = h01;
            *(__nv_bfloat162*)(smc + off + 4)         = h23;
            *(__nv_bfloat162*)(smc + PLANE + off)     = l01;
            *(__nv_bfloat162*)(smc + PLANE + off + 4) = l23;
        }
        CP_WAIT0();
        __syncthreads();
    }

    for (int ch = 0; ch < 12; ch++) {
        int s = ch & 1;
        int have_next = (ch + 1 < 12);
        if (have_next) {
            int nc = ch + 1;
            const float4* S4 = (const float4*)srcs[nc >> 2];
            int k4off = (nc & 3) * 8;
#pragma unroll
            for (int i = 0; i < 4; i++) {
                int rg = m0 + rb + 32 * i;
                pa[i] = (rg < NN) ? S4[(size_t)rg * 32 + k4off + q]
                                  : make_float4(0.f, 0.f, 0.f, 0.f);
            }
            uint32_t st = sb + (1 - s) * STAGE;
            uint32_t dBH = st + 2 * PLANE, dBL = st + 3 * PLANE;
            int gk = nc * 64;
            CP_ASYNC16(dBH + n0 * BSTR + p0 * 16, BhC + n0 * 768 + gk + p0 * 16);
            CP_ASYNC16(dBH + n1 * BSTR + p1 * 16, BhC + n1 * 768 + gk + p1 * 16);
            CP_ASYNC16(dBL + n0 * BSTR + p0 * 16, BlC + n0 * 768 + gk + p0 * 16);
            CP_ASYNC16(dBL + n1 * BSTR + p1 * 16, BlC + n1 * 768 + gk + p1 * 16);
            CP_COMMIT();
        }

        uint32_t st = sb + s * STAGE;
        uint32_t aAH = st, aAL = st + PLANE, aBH = st + 2 * PLANE, aBL = st + 3 * PLANE;
#pragma unroll
        for (int ks = 0; ks < 2; ks++) {
            uint32_t ah[2][4], al[2][4], bh[8][2], bl[8][2];
            uint32_t aoff = (uint32_t)((wm + (lane & 15)) * BSTR
                          + ks * 32 + (lane >> 4) * 16);
            ldsm4(ah[0], aAH + aoff);
            ldsm4(ah[1], aAH + aoff + 16 * BSTR);
            ldsm4(al[0], aAL + aoff);
            ldsm4(al[1], aAL + aoff + 16 * BSTR);
            uint32_t boff = (uint32_t)((wn + ((lane >> 4) << 3) + (lane & 7)) * BSTR
                          + ks * 32 + ((lane >> 3) & 1) * 16);
#pragma unroll
            for (int p = 0; p < 4; p++) {
                uint32_t r4[4];
                ldsm4(r4, aBH + boff + p * 16 * BSTR);
                bh[2*p][0] = r4[0]; bh[2*p][1] = r4[1];
                bh[2*p+1][0] = r4[2]; bh[2*p+1][1] = r4[3];
                ldsm4(r4, aBL + boff + p * 16 * BSTR);
                bl[2*p][0] = r4[0]; bl[2*p][1] = r4[1];
                bl[2*p+1][0] = r4[2]; bl[2*p+1][1] = r4[3];
            }
#pragma unroll
            for (int mi = 0; mi < 2; mi++)
#pragma unroll
                for (int nj = 0; nj < 8; nj++) {
                    mma16816(acc[mi][nj], ah[mi], bh[nj]);
                    mma16816(acc[mi][nj], ah[mi], bl[nj]);
                    mma16816(acc[mi][nj], al[mi], bh[nj]);
                }
        }

        if (have_next) {
            char* stc = smc + (1 - s) * STAGE;
#pragma unroll
            for (int i = 0; i < 4; i++) {
                float4 v = pa[i];
                __nv_bfloat162 h01 = __floats2bfloat162_rn(v.x, v.y);
                __nv_bfloat162 h23 = __floats2bfloat162_rn(v.z, v.w);
                __nv_bfloat162 l01 = __floats2bfloat162_rn(v.x - __bfloat162float(h01.x),
                                                           v.y - __bfloat162float(h01.y));
                __nv_bfloat162 l23 = __floats2bfloat162_rn(v.z - __bfloat162float(h23.x),
                                                           v.w - __bfloat162float(h23.y));
                int off = (rb + 32 * i) * BSTR + q * 8;
                *(__nv_bfloat162*)(stc + off)             = h01;
                *(__nv_bfloat162*)(stc + off + 4)         = h23;
                *(__nv_bfloat162*)(stc + PLANE + off)     = l01;
                *(__nv_bfloat162*)(stc + PLANE + off + 4) = l23;
            }
            CP_WAIT0();
            __syncthreads();
        }
    }

#pragma unroll
    for (int mi = 0; mi < 2; mi++) {
        int r0 = m0 + wm + mi * 16 + (lane >> 2);
#pragma unroll
        for (int nj = 0; nj < 8; nj++) {
            int c = wn + nj * 8 + 2 * (lane & 3);
            float bx = __ldg(bias + c), by = __ldg(bias + c + 1);
            if (r0 < NN) {
                float2 o;
                o.x = fmaxf(acc[mi][nj][0] + bx, 0.f);
                o.y = fmaxf(acc[mi][nj][1] + by, 0.f);
                *(float2*)(out + (size_t)r0 * CC + c) = o;
            }
            if (r0 + 8 < NN) {
                float2 o;
                o.x = fmaxf(acc[mi][nj][2] + bx, 0.f);
                o.y = fmaxf(acc[mi][nj][3] + by, 0.f);
                *(float2*)(out + (size_t)(r0 + 8) * CC + c) = o;
            }
        }
    }
}

// fused tail at FULL statspool parallelism: 391 blocks x 128 threads.
// zero -> stats/pool/cnt (one 128-row tile per block) -> bnprep -> mlp
__global__ void __launch_bounds__(128)
k_tail2(const float* __restrict__ h, const int* __restrict__ batch,
        const float* __restrict__ gamma, const float* __restrict__ beta,
        const float* __restrict__ lw1, const float* __restrict__ lb1,
        const float* __restrict__ lw2, const float* __restrict__ lb2,
        float* __restrict__ out) {
    int tid = threadIdx.x, b = blockIdx.x;
    int gt = b * 128 + tid;
    const int GT = TLB2 * 128;

    // A: zero reduction buffers (grid-stride over 50k threads)
    for (int i = gt; i < GG * CC; i += GT) g_pool[i] = 0.f;
    if (gt < GG) g_cnt[gt] = 0.f;
    if (gt < CC) { g_chsum[gt] = 0.f; g_chsq[gt] = 0.f; }
    gridbar(&g_syncT[0], TLB2);

    // B: stats + pool + cnt — exactly one 128-row tile per block (R13 parallelism)
    {
        int c = tid;
        int base = b * 128;
        float s = 0.f, sq = 0.f, acc = 0.f, cacc = 0.f;
        int cur = -1;
        for (int r = 0; r < 128; r++) {
            int n = base + r;
            if (n >= NN) break;
            int g = batch[n];
            float v = h[(size_t)n * CC + c];
            s += v;
            sq += v * v;
            if (g != cur) {
                if (cur >= 0) {
                    atomicAdd(&g_pool[cur * CC + c], acc);
                    if (c == 0) atomicAdd(&g_cnt[cur], cacc);
                }
                cur = g;
                acc = 0.f;
                cacc = 0.f;
            }
            acc += v;
            cacc += 1.f;
        }
        if (cur >= 0) {
            atomicAdd(&g_pool[cur * CC + c], acc);
            if (c == 0) atomicAdd(&g_cnt[cur], cacc);
        }
        atomicAdd(&g_chsum[c], s);
        atomicAdd(&g_chsq[c], sq);
    }
    gridbar(&g_syncT[1], TLB2);

    // C: BN fold (block 0)
    if (b == 0) {
        int c = tid;
        float mu = g_chsum[c] * (1.0f / NN);
        float var = fmaxf(g_chsq[c] * (1.0f / NN) - mu * mu, 0.f);
        float inv = rsqrtf(var + 1e-5f);
        float a = gamma[c] * inv;
        g_bna[c] = a;
        g_bnb[c] = beta[c] - mu * a;
    }
    gridbar(&g_syncT[2], TLB2);

    // D: head MLP (one thread per graph; blocks 0-3)
    int g = gt;
    if (g < GG) {
        float inv = 1.0f / fmaxf(g_cnt[g], 1.0f);
        float hid[16];
#pragma unroll
        for (int j = 0; j < 16; j++) hid[j] = lb1[j];
#pragma unroll 4
        for (int cc2 = 0; cc2 < CC; cc2++) {
            float pb = g_pool[g * CC + cc2] * inv * g_bna[cc2] + g_bnb[cc2];
            const float4* w4 = (const float4*)(lw1 + cc2 * 16);
#pragma unroll
            for (int qq = 0; qq < 4; qq++) {
                float4 w = w4[qq];
                hid[qq * 4 + 0] += pb * w.x;
                hid[qq * 4 + 1] += pb * w.y;
                hid[qq * 4 + 2] += pb * w.z;
                hid[qq * 4 + 3] += pb * w.w;
            }
        }
        float o0 = lb2[0], o1 = lb2[1];
#pragma unroll
        for (int j = 0; j < 16; j++) {
            float r = fmaxf(hid[j], 0.f);
            o0 += r * lw2[j * 2 + 0];
            o1 += r * lw2[j * 2 + 1];
        }
        out[g * 2 + 0] = o0;
        out[g * 2 + 1] = o1;
    }
    gridexit(&g_syncT[3], g_syncT, 8, TLB2, b);
}

// ---------------- launcher ----------------
extern "C" void kernel_launch(void* const* d_in, const int* in_sizes, int n_in,
                              void* d_out, int out_size) {
    const float* atom_emb = (const float*)d_in[0];
    const float* W1   = (const float*)d_in[1];
    const float* b1   = (const float*)d_in[2];
    const float* W3   = (const float*)d_in[3];
    const float* b3   = (const float*)d_in[4];
    const float* gam  = (const float*)d_in[5];
    const float* bet  = (const float*)d_in[6];
    const float* lw1  = (const float*)d_in[7];
    const float* lb1  = (const float*)d_in[8];
    const float* lw2  = (const float*)d_in[9];
    const float* lb2  = (const float*)d_in[10];
    const int*   x    = (const int*)d_in[11];
    const int*   ei   = (const int*)d_in[12];
    const int*   batch= (const int*)d_in[13];
    const int* row = ei;
    const int* col = ei + EE;
    float* out = (float*)d_out;

    float *h0, *h1, *t1, *t2;
    __nv_bfloat16 *Bh, *Bl;
    cudaGetSymbolAddress((void**)&h0, g_h0);
    cudaGetSymbolAddress((void**)&h1, g_h1);
    cudaGetSymbolAddress((void**)&t1, g_t1);
    cudaGetSymbolAddress((void**)&t2, g_t2);
    cudaGetSymbolAddress((void**)&Bh, g_Bh);
    cudaGetSymbolAddress((void**)&Bl, g_Bl);

    const int GEMM_SMEM = 2 * STAGE;   // 81920 B, 2 CTAs/SM
    cudaFuncSetAttribute(k_gemm, cudaFuncAttributeMaxDynamicSharedMemorySize, GEMM_SMEM);

    const int MM_B = (NN + 127) / 128;          // 391 tiles

    // (1) CSR build + both weight folds
    k_csr<<<CSRB, 256>>>(row, col, W1, W3);

    // (2) embed + conv1 double SpMV, (3) GEMM
    k_spmv2<<<SPB, 256>>>(h0, t1, t2, atom_emb, x, 1);
    k_gemm<<<MM_B, 256, GEMM_SMEM>>>(h0, t1, t2, Bh, Bl, b1, h1);

    // (4) conv2 double SpMV, (5) GEMM (conv3 weights), writes into h0
    k_spmv2<<<SPB, 256>>>(h1, t1, t2, atom_emb, x, 0);
    k_gemm<<<MM_B, 256, GEMM_SMEM>>>(h1, t1, t2, Bh + (size_t)CC * 384,
                                     Bl + (size_t)CC * 384, b3, h0);

    // (6) fused tail: zero + stats/pool/cnt + bnprep + mlp (full parallelism)
    k_tail2<<<TLB2, 128>>>(h0, batch, gam, bet, lw1, lb1, lw2, lb2, out);
}